// round 1
// baseline (speedup 1.0000x reference)
#include <cuda_runtime.h>
#include <cstddef>

#define N_NODES 50000
#define N_EDGES 800000
#define FEAT    128
#define HEADS   8
#define HDIM    16
#define NEG_SLOPE 0.2f

// ---------------- device scratch (no dynamic allocation allowed) -------------
__device__ float g_feat_src[(size_t)N_NODES * FEAT];    // 25.6 MB
__device__ float g_feat_dst[(size_t)N_NODES * FEAT];    // 25.6 MB
__device__ float g_feat_edge[(size_t)N_EDGES * FEAT];   // 409.6 MB
__device__ float g_z[(size_t)N_NODES * HEADS];          // 1.6 MB

// ---------------- K0: zero accumulators -------------------------------------
__global__ void zero_kernel(float* __restrict__ out)
{
    int i = blockIdx.x * blockDim.x + threadIdx.x;
    if (i < N_NODES * FEAT) out[i] = 0.0f;
    if (i < N_NODES * HEADS) g_z[i] = 0.0f;
}

// ---------------- K1: C[M,128] = A[M,128] @ W[128,128]^T (+bias) -------------
// Register-blocked SGEMM: BM=BN=128, BK=16, 256 threads, 8x8 per thread.
// Fragment mapping is split (cols tx*4 and 64+tx*4) so compute-phase LDS.128
// is conflict-free across the warp.
__global__ __launch_bounds__(256) void gemm128_nt(
    const float* __restrict__ A, const float* __restrict__ W,
    const float* __restrict__ bias, float* __restrict__ C, int M)
{
    __shared__ float As[16][132];
    __shared__ float Bs[16][132];

    const int tid = threadIdx.x;
    const int tx = tid & 15;
    const int ty = tid >> 4;
    const int bm = blockIdx.x * 128;

    float acc[8][8];
#pragma unroll
    for (int i = 0; i < 8; i++)
#pragma unroll
        for (int j = 0; j < 8; j++) acc[i][j] = 0.0f;

    for (int kt = 0; kt < 128; kt += 16) {
        // load 128x16 tiles of A and W (as float4 along k), store k-major
#pragma unroll
        for (int r = 0; r < 2; r++) {
            int idx = tid * 2 + r;          // 0..511
            int row = idx >> 2;             // 0..127
            int c4  = (idx & 3) << 2;       // 0,4,8,12
            float4 av = make_float4(0.f, 0.f, 0.f, 0.f);
            if (bm + row < M)
                av = *(const float4*)(A + (size_t)(bm + row) * 128 + kt + c4);
            As[c4 + 0][row] = av.x; As[c4 + 1][row] = av.y;
            As[c4 + 2][row] = av.z; As[c4 + 3][row] = av.w;
            float4 wv = *(const float4*)(W + (size_t)row * 128 + kt + c4);
            Bs[c4 + 0][row] = wv.x; Bs[c4 + 1][row] = wv.y;
            Bs[c4 + 2][row] = wv.z; Bs[c4 + 3][row] = wv.w;
        }
        __syncthreads();

#pragma unroll
        for (int kk = 0; kk < 16; kk++) {
            float a[8], b[8];
            *(float4*)&a[0] = *(const float4*)&As[kk][ty * 4];
            *(float4*)&a[4] = *(const float4*)&As[kk][64 + ty * 4];
            *(float4*)&b[0] = *(const float4*)&Bs[kk][tx * 4];
            *(float4*)&b[4] = *(const float4*)&Bs[kk][64 + tx * 4];
#pragma unroll
            for (int i = 0; i < 8; i++)
#pragma unroll
                for (int j = 0; j < 8; j++)
                    acc[i][j] = fmaf(a[i], b[j], acc[i][j]);
        }
        __syncthreads();
    }

    float bcol[8];
#pragma unroll
    for (int j = 0; j < 8; j++) {
        int col = (j < 4) ? (tx * 4 + j) : (64 + tx * 4 + (j - 4));
        bcol[j] = bias ? bias[col] : 0.0f;
    }
#pragma unroll
    for (int i = 0; i < 8; i++) {
        int row = (i < 4) ? (bm + ty * 4 + i) : (bm + 64 + ty * 4 + (i - 4));
        if (row < M) {
            float4 v0 = make_float4(acc[i][0] + bcol[0], acc[i][1] + bcol[1],
                                    acc[i][2] + bcol[2], acc[i][3] + bcol[3]);
            float4 v1 = make_float4(acc[i][4] + bcol[4], acc[i][5] + bcol[5],
                                    acc[i][6] + bcol[6], acc[i][7] + bcol[7]);
            *(float4*)(C + (size_t)row * 128 + tx * 4) = v0;
            *(float4*)(C + (size_t)row * 128 + 64 + tx * 4) = v1;
        }
    }
}

// ---------------- K2: fused per-edge score + message scatter -----------------
// One warp per edge. Lane t handles dims 4t..4t+3 (head = t/4).
// score_h = sum_d lrelu(fs+fd+fe)*attn ; p = exp(score)
// scatter p into z[dst,h] and p*(fs+fe) into out[dst,:] (unnormalized).
__global__ __launch_bounds__(256) void edge_pass(
    const int* __restrict__ src, const int* __restrict__ dst,
    const float* __restrict__ attn, float* __restrict__ out)
{
    int e = blockIdx.x * 8 + (threadIdx.x >> 5);
    if (e >= N_EDGES) return;
    int lane = threadIdx.x & 31;

    int s = __ldg(src + e);
    int d = __ldg(dst + e);

    const float4 fs = *(const float4*)(g_feat_src + (size_t)s * FEAT + lane * 4);
    const float4 fd = *(const float4*)(g_feat_dst + (size_t)d * FEAT + lane * 4);
    const float4 fe = *(const float4*)(g_feat_edge + (size_t)e * FEAT + lane * 4);
    const float4 at = *(const float4*)(attn + lane * 4);

    float t0 = fs.x + fd.x + fe.x;
    float t1 = fs.y + fd.y + fe.y;
    float t2 = fs.z + fd.z + fe.z;
    float t3 = fs.w + fd.w + fe.w;
    float l0 = (t0 >= 0.f) ? t0 : NEG_SLOPE * t0;
    float l1 = (t1 >= 0.f) ? t1 : NEG_SLOPE * t1;
    float l2 = (t2 >= 0.f) ? t2 : NEG_SLOPE * t2;
    float l3 = (t3 >= 0.f) ? t3 : NEG_SLOPE * t3;

    float p = l0 * at.x + l1 * at.y + l2 * at.z + l3 * at.w;
    // butterfly within the 4-lane quad (one head): all quad lanes get the sum
    p += __shfl_xor_sync(0xffffffffu, p, 1);
    p += __shfl_xor_sync(0xffffffffu, p, 2);

    float ex = __expf(p);

    if ((lane & 3) == 0)
        atomicAdd(&g_z[(size_t)d * HEADS + (lane >> 2)], ex);

    float mx = (fs.x + fe.x) * ex;
    float my = (fs.y + fe.y) * ex;
    float mz = (fs.z + fe.z) * ex;
    float mw = (fs.w + fe.w) * ex;

    float* op = out + (size_t)d * FEAT + lane * 4;
    asm volatile("red.global.add.v4.f32 [%0], {%1,%2,%3,%4};"
                 :: "l"(op), "f"(mx), "f"(my), "f"(mz), "f"(mw)
                 : "memory");
}

// ---------------- K3: finalize out = relu(acc / z) ---------------------------
__global__ void finalize(float* __restrict__ out)
{
    int i = blockIdx.x * blockDim.x + threadIdx.x;   // one per float4
    if (i >= N_NODES * 32) return;
    int n = i >> 5;
    int q = i & 31;           // 0..31 -> dims q*4
    int h = q >> 2;
    float z = g_z[(size_t)n * HEADS + h];
    float inv = (z > 0.f) ? (1.f / z) : 0.f;
    float4 v = *(float4*)(out + (size_t)n * FEAT + q * 4);
    v.x = fmaxf(v.x * inv, 0.f);
    v.y = fmaxf(v.y * inv, 0.f);
    v.z = fmaxf(v.z * inv, 0.f);
    v.w = fmaxf(v.w * inv, 0.f);
    *(float4*)(out + (size_t)n * FEAT + q * 4) = v;
}

// ---------------- launch -----------------------------------------------------
extern "C" void kernel_launch(void* const* d_in, const int* in_sizes, int n_in,
                              void* d_out, int out_size)
{
    const float* x      = (const float*)d_in[0];
    const float* efeat  = (const float*)d_in[1];
    const int*   src    = (const int*)d_in[2];
    const int*   dst    = (const int*)d_in[3];
    const float* W_src  = (const float*)d_in[4];
    const float* b_src  = (const float*)d_in[5];
    const float* W_dst  = (const float*)d_in[6];
    const float* b_dst  = (const float*)d_in[7];
    const float* W_edge = (const float*)d_in[8];
    const float* attn   = (const float*)d_in[9];
    float* out = (float*)d_out;

    float *p_fsrc = nullptr, *p_fdst = nullptr, *p_fedge = nullptr;
    cudaGetSymbolAddress((void**)&p_fsrc, g_feat_src);
    cudaGetSymbolAddress((void**)&p_fdst, g_feat_dst);
    cudaGetSymbolAddress((void**)&p_fedge, g_feat_edge);

    // K0: zero d_out and g_z
    {
        int total = N_NODES * FEAT;
        zero_kernel<<<(total + 255) / 256, 256>>>(out);
    }
    // K1: projections
    {
        int nb_node = (N_NODES + 127) / 128;   // 391
        int nb_edge = (N_EDGES + 127) / 128;   // 6250
        gemm128_nt<<<nb_node, 256>>>(x, W_src, b_src, p_fsrc, N_NODES);
        gemm128_nt<<<nb_node, 256>>>(x, W_dst, b_dst, p_fdst, N_NODES);
        gemm128_nt<<<nb_edge, 256>>>(efeat, W_edge, nullptr, p_fedge, N_EDGES);
    }
    // K2: fused per-edge score + scatter (warp per edge)
    {
        int nb = (N_EDGES + 7) / 8;            // 100000 blocks x 256 thr
        edge_pass<<<nb, 256>>>(src, dst, attn, out);
    }
    // K3: normalize + relu
    {
        int total = N_NODES * 32;
        finalize<<<(total + 255) / 256, 256>>>(out);
    }
}